// round 3
// baseline (speedup 1.0000x reference)
#include <cuda_runtime.h>
#include <cuda_bf16.h>

#define NNODES 100000
#define NEDGES 600000
#define DFEAT  128

// Scratch (allocation-free rule: __device__ globals, referenced by symbol only)
__device__ float g_dis[NNODES];   // deg -> rsqrt(deg)
__device__ float g_h0[NNODES];    // y = X w
__device__ float g_h1[NNODES];    // after round 1

// ---------------- degree / normalization ----------------

__global__ void k_init_deg() {
    int i = blockIdx.x * blockDim.x + threadIdx.x;
    if (i < NNODES) g_dis[i] = 1.0f;  // self-loop contribution
}

__global__ void k_count_deg(const int* __restrict__ ei) {
    int e = blockIdx.x * blockDim.x + threadIdx.x;
    if (e < NEDGES) {
        int col = ei[NEDGES + e];
        atomicAdd(&g_dis[col], 1.0f);
    }
}

__global__ void k_rsqrt_deg() {
    int i = blockIdx.x * blockDim.x + threadIdx.x;
    if (i < NNODES) g_dis[i] = rsqrtf(g_dis[i]);  // deg >= 1 always (self-loop)
}

// ---------------- y = X w (warp per node, float4) ----------------

__global__ void k_dot(const float* __restrict__ x, const float* __restrict__ w) {
    int warp_id = (blockIdx.x * blockDim.x + threadIdx.x) >> 5;
    int lane = threadIdx.x & 31;
    if (warp_id >= NNODES) return;

    const float4* xr = reinterpret_cast<const float4*>(x + (size_t)warp_id * DFEAT);
    const float4* wr = reinterpret_cast<const float4*>(w);

    float4 xv = xr[lane];        // lane l covers features [4l, 4l+4)
    float4 wv = __ldg(&wr[lane]);

    float s = xv.x * wv.x + xv.y * wv.y + xv.z * wv.z + xv.w * wv.w;
    #pragma unroll
    for (int off = 16; off > 0; off >>= 1)
        s += __shfl_xor_sync(0xFFFFFFFFu, s, off);

    if (lane == 0) g_h0[warp_id] = s;
}

// ---------------- propagation round 1: h1 = S h0 ----------------

__global__ void k_prop_init_1() {
    int i = blockIdx.x * blockDim.x + threadIdx.x;
    if (i < NNODES) {
        float d = g_dis[i];
        g_h1[i] = d * d * g_h0[i];
    }
}

__global__ void k_prop_edges_1(const int* __restrict__ ei) {
    int e = blockIdx.x * blockDim.x + threadIdx.x;
    if (e < NEDGES) {
        int row = ei[e];
        int col = ei[NEDGES + e];
        float v = __ldg(&g_dis[row]) * __ldg(&g_dis[col]) * __ldg(&g_h0[row]);
        atomicAdd(&g_h1[col], v);
    }
}

// ---------------- propagation round 2: out = S h1 + b ----------------

__global__ void k_prop_init_2(float* __restrict__ out, const float* __restrict__ b) {
    int i = blockIdx.x * blockDim.x + threadIdx.x;
    if (i < NNODES) {
        float d = g_dis[i];
        out[i] = d * d * g_h1[i] + b[0];
    }
}

__global__ void k_prop_edges_2(const int* __restrict__ ei,
                               float* __restrict__ out) {
    int e = blockIdx.x * blockDim.x + threadIdx.x;
    if (e < NEDGES) {
        int row = ei[e];
        int col = ei[NEDGES + e];
        float v = __ldg(&g_dis[row]) * __ldg(&g_dis[col]) * __ldg(&g_h1[row]);
        atomicAdd(&out[col], v);
    }
}

// ---------------- launch ----------------

extern "C" void kernel_launch(void* const* d_in, const int* in_sizes, int n_in,
                              void* d_out, int out_size) {
    const float* x  = (const float*)d_in[0];
    const int*   ei = (const int*)d_in[1];
    const float* W  = (const float*)d_in[2];
    const float* b  = (const float*)d_in[3];
    float* out = (float*)d_out;

    const int T = 256;
    const int gN = (NNODES + T - 1) / T;
    const int gE = (NEDGES + T - 1) / T;
    const int gDot = (NNODES * 32 + T - 1) / T;  // warp per node

    // normalization
    k_init_deg<<<gN, T>>>();
    k_count_deg<<<gE, T>>>(ei);
    k_rsqrt_deg<<<gN, T>>>();

    // y = X w
    k_dot<<<gDot, T>>>(x, W);

    // round 1: h1 = S h0
    k_prop_init_1<<<gN, T>>>();
    k_prop_edges_1<<<gE, T>>>(ei);

    // round 2: out = S h1 + b
    k_prop_init_2<<<gN, T>>>(out, b);
    k_prop_edges_2<<<gE, T>>>(ei, out);
}

// round 4
// speedup vs baseline: 1.1749x; 1.1749x over previous
#include <cuda_runtime.h>
#include <cuda_bf16.h>

#define NNODES 100000
#define NEDGES 600000
#define DFEAT  128

// Scratch (__device__ globals; never materialized host-side)
__device__ float g_dis[NNODES];   // deg -> rsqrt(deg)
__device__ float g_h0[NNODES];    // y = X w
__device__ float g_h1[NNODES];    // after round 1

// K1: init deg=1 (self loop), zero h1, out = b
__global__ void k_init(float* __restrict__ out, const float* __restrict__ b) {
    int i = blockIdx.x * blockDim.x + threadIdx.x;
    if (i < NNODES) {
        g_dis[i] = 1.0f;
        g_h1[i]  = 0.0f;
        out[i]   = b[0];
    }
}

// K2: degree count via atomics on col
__global__ void k_count_deg(const int* __restrict__ ei) {
    int e = blockIdx.x * blockDim.x + threadIdx.x;
    if (e < NEDGES) {
        atomicAdd(&g_dis[ei[NEDGES + e]], 1.0f);
    }
}

// K3: y = X w, 4 nodes per warp (MLP=4), plus dis = rsqrt(deg)
__global__ void k_dot(const float* __restrict__ x, const float* __restrict__ w) {
    int warp_id = (blockIdx.x * blockDim.x + threadIdx.x) >> 5;
    int lane = threadIdx.x & 31;
    int base = warp_id * 4;
    if (base >= NNODES) return;   // NNODES % 4 == 0: full quads always

    // fold in normalization: 4 lanes convert this warp's 4 deg entries
    if (lane < 4) g_dis[base + lane] = rsqrtf(g_dis[base + lane]);

    const float4* wr = reinterpret_cast<const float4*>(w);
    float4 wv = __ldg(&wr[lane]);

    // 4 independent row loads -> 4 outstanding LDG.128 per thread
    float4 xv0 = reinterpret_cast<const float4*>(x + (size_t)(base + 0) * DFEAT)[lane];
    float4 xv1 = reinterpret_cast<const float4*>(x + (size_t)(base + 1) * DFEAT)[lane];
    float4 xv2 = reinterpret_cast<const float4*>(x + (size_t)(base + 2) * DFEAT)[lane];
    float4 xv3 = reinterpret_cast<const float4*>(x + (size_t)(base + 3) * DFEAT)[lane];

    float s0 = xv0.x * wv.x + xv0.y * wv.y + xv0.z * wv.z + xv0.w * wv.w;
    float s1 = xv1.x * wv.x + xv1.y * wv.y + xv1.z * wv.z + xv1.w * wv.w;
    float s2 = xv2.x * wv.x + xv2.y * wv.y + xv2.z * wv.z + xv2.w * wv.w;
    float s3 = xv3.x * wv.x + xv3.y * wv.y + xv3.z * wv.z + xv3.w * wv.w;

    #pragma unroll
    for (int off = 16; off > 0; off >>= 1) {
        s0 += __shfl_xor_sync(0xFFFFFFFFu, s0, off);
        s1 += __shfl_xor_sync(0xFFFFFFFFu, s1, off);
        s2 += __shfl_xor_sync(0xFFFFFFFFu, s2, off);
        s3 += __shfl_xor_sync(0xFFFFFFFFu, s3, off);
    }

    if (lane == 0) {
        *reinterpret_cast<float4*>(&g_h1[0] + 0) = *reinterpret_cast<float4*>(&g_h1[0] + 0); // no-op guard (removed by compiler)
        float4 r = make_float4(s0, s1, s2, s3);
        *reinterpret_cast<float4*>(&g_h0[base]) = r;  // base % 4 == 0 -> 16B aligned
    }
}

// K4: round 1, fused self + edge scatter into h1 (h1 pre-zeroed in K1)
// NNODES % 32 == 0 -> warps never straddle the N/E split; index loads coalesced
__global__ void k_round1(const int* __restrict__ ei) {
    int t = blockIdx.x * blockDim.x + threadIdx.x;
    if (t < NNODES) {
        float d = g_dis[t];
        atomicAdd(&g_h1[t], d * d * g_h0[t]);
    } else {
        int e = t - NNODES;
        if (e < NEDGES) {
            int row = __ldg(&ei[e]);
            int col = __ldg(&ei[NEDGES + e]);
            float v = __ldg(&g_dis[row]) * __ldg(&g_dis[col]) * __ldg(&g_h0[row]);
            atomicAdd(&g_h1[col], v);
        }
    }
}

// K5: round 2, fused self + edge scatter into out (out pre-set to b in K1)
__global__ void k_round2(const int* __restrict__ ei, float* __restrict__ out) {
    int t = blockIdx.x * blockDim.x + threadIdx.x;
    if (t < NNODES) {
        float d = g_dis[t];
        atomicAdd(&out[t], d * d * g_h1[t]);
    } else {
        int e = t - NNODES;
        if (e < NEDGES) {
            int row = __ldg(&ei[e]);
            int col = __ldg(&ei[NEDGES + e]);
            float v = __ldg(&g_dis[row]) * __ldg(&g_dis[col]) * __ldg(&g_h1[row]);
            atomicAdd(&out[col], v);
        }
    }
}

extern "C" void kernel_launch(void* const* d_in, const int* in_sizes, int n_in,
                              void* d_out, int out_size) {
    const float* x  = (const float*)d_in[0];
    const int*   ei = (const int*)d_in[1];
    const float* W  = (const float*)d_in[2];
    const float* b  = (const float*)d_in[3];
    float* out = (float*)d_out;

    const int T = 256;
    const int gN  = (NNODES + T - 1) / T;
    const int gE  = (NEDGES + T - 1) / T;
    const int gNE = (NNODES + NEDGES + T - 1) / T;
    const int gDot = ((NNODES / 4) * 32 + T - 1) / T;  // warp per 4 nodes

    k_init<<<gN, T>>>(out, b);
    k_count_deg<<<gE, T>>>(ei);
    k_dot<<<gDot, T>>>(x, W);
    k_round1<<<gNE, T>>>(ei);
    k_round2<<<gNE, T>>>(ei, out);
}